// round 10
// baseline (speedup 1.0000x reference)
#include <cuda_runtime.h>
#include <cstdint>

#define NB 8
#define NS 2048
#define NH 8
#define NDK 64
#define NDE 512

// ---------------- scratch (device globals; no allocations allowed) ----------
__device__ float g_qs[NB * NH * NS * NDK];   // 32 MB, pre-scaled by 1/8
__device__ float g_ks[NB * NH * NS * NDK];   // 32 MB
__device__ float g_vs[NB * NH * NS * NDK];   // 32 MB
__device__ float g_ctx[NB * NS * NDE];       // 32 MB
__device__ float g_rl[NB * NH * NS];         // 512 KB: 1/rowsum per (b,h,s)

// ---------------- fast exp: FFMA-pipe polynomial (MUFU is slow on sm_103a) --
__device__ __forceinline__ float fexp(float x) {
    float y = x * 1.4426950408889634f;          // log2(e)
    y = fminf(fmaxf(y, -120.0f), 120.0f);
    float t = y + 12582912.0f;                  // round-to-nearest-int trick
    float r = t - 12582912.0f;
    float f = y - r;                            // f in [-0.5, 0.5]
    int   ei = __float_as_int(t) - 0x4B400000;  // integer value of r
    float p = 1.3333558146e-3f;
    p = fmaf(p, f, 9.6181291076e-3f);
    p = fmaf(p, f, 5.5504108665e-2f);
    p = fmaf(p, f, 2.4022650696e-1f);
    p = fmaf(p, f, 6.9314718056e-1f);
    p = fmaf(p, f, 1.0f);
    return p * __int_as_float((ei + 127) << 23);
}

// ---------------- kernel 1: projections q_s/k_s/v_s = X @ Wq + bq -----------
__global__ __launch_bounds__(256) void k_proj(
    const float* __restrict__ Q, const float* __restrict__ K,
    const float* __restrict__ V, const float* __restrict__ W,
    const float* __restrict__ bias)
{
    const int which = blockIdx.z;
    const float* X = (which == 0) ? Q : (which == 1) ? K : V;
    float* O = (which == 0) ? g_qs : (which == 1) ? g_ks : g_vs;
    const float scl = (which == 0) ? 0.125f : 1.0f;

    __shared__ float As[16][64];   // [k][m] (transposed)
    __shared__ float Bs[16][64];   // [k][n]

    const int tid = threadIdx.x;
    const int tx = tid & 15, ty = tid >> 4;
    const int m0 = blockIdx.y * 64, n0 = blockIdx.x * 64;

    float acc[4][4] = {};

    for (int k0 = 0; k0 < NDE; k0 += 16) {
        {
            int r = tid >> 2;
            int c = (tid & 3) * 4;
            float4 a = *(const float4*)(X + (size_t)(m0 + r) * NDE + k0 + c);
            As[c + 0][r] = a.x; As[c + 1][r] = a.y;
            As[c + 2][r] = a.z; As[c + 3][r] = a.w;
        }
        {
            int r = tid >> 4;
            int c = (tid & 15) * 4;
            *(float4*)&Bs[r][c] = *(const float4*)(W + (size_t)(k0 + r) * NDE + n0 + c);
        }
        __syncthreads();
        #pragma unroll
        for (int kk = 0; kk < 16; kk++) {
            float4 a = *(const float4*)&As[kk][ty * 4];
            float4 b = *(const float4*)&Bs[kk][tx * 4];
            float av[4] = {a.x, a.y, a.z, a.w};
            float bv[4] = {b.x, b.y, b.z, b.w};
            #pragma unroll
            for (int i = 0; i < 4; i++)
                #pragma unroll
                for (int j = 0; j < 4; j++)
                    acc[i][j] = fmaf(av[i], bv[j], acc[i][j]);
        }
        __syncthreads();
    }

    const int hh = n0 >> 6;                  // whole tile is one head
    float4 bi = *(const float4*)(bias + n0 + tx * 4);
    #pragma unroll
    for (int i = 0; i < 4; i++) {
        int m = m0 + ty * 4 + i;
        int bb = m >> 11;
        int ss = m & 2047;
        float4 o;
        o.x = (acc[i][0] + bi.x) * scl;
        o.y = (acc[i][1] + bi.y) * scl;
        o.z = (acc[i][2] + bi.z) * scl;
        o.w = (acc[i][3] + bi.w) * scl;
        *(float4*)(O + ((size_t)(bb * NH + hh) * NS + ss) * NDK + tx * 4) = o;
    }
}

// ---------------- kernel 2a: row sums only (QK + exp, NO weight stores) -----
// grid (NS/128, NH, NB), 256 threads. Light smem -> higher occupancy.
// Accumulation order matches pass 2 exactly (bitwise-identical sums).
__global__ __launch_bounds__(256) void k_rsum(const unsigned char* __restrict__ mask)
{
    extern __shared__ float sm[];
    float* Qs = sm;            // [64][128]  (d-major, transposed)
    float* Ks = sm + 8192;     // [64][64]   (d-major, transposed)
    float* ls = sm + 12288;    // [128]

    const int qt = blockIdx.x, h = blockIdx.y, b = blockIdx.z;
    const float* qsp = g_qs + (((size_t)(b * NH + h) * NS) + qt * 128) * NDK;
    const float* ksp = g_ks + ((size_t)(b * NH + h) * NS) * NDK;
    const unsigned char* mrow = mask + ((size_t)b * NS + qt * 128) * NS;

    const int tid = threadIdx.x;
    const int tx = tid & 15;        // k-col group (4 cols)
    const int ty = tid >> 4;        // q-row group (8 rows)

    // ---- load Q tile transposed -> Qs[d][qi]
    {
        int r = tid >> 1;
        int cb = (tid & 1) * 32;
        #pragma unroll
        for (int cc = 0; cc < 32; cc += 4) {
            float4 a = *(const float4*)(qsp + (size_t)r * NDK + cb + cc);
            Qs[(cb + cc + 0) * 128 + r] = a.x;
            Qs[(cb + cc + 1) * 128 + r] = a.y;
            Qs[(cb + cc + 2) * 128 + r] = a.z;
            Qs[(cb + cc + 3) * 128 + r] = a.w;
        }
    }

    float rsum[8];
    #pragma unroll
    for (int i = 0; i < 8; i++) rsum[i] = 0.0f;

    for (int kt = 0; kt < NS; kt += 64) {
        __syncthreads();
        {
            int r = tid & 63;
            int cb = (tid >> 6) * 16;
            #pragma unroll
            for (int cc = 0; cc < 16; cc += 4) {
                float4 a = *(const float4*)(ksp + (size_t)(kt + r) * NDK + cb + cc);
                Ks[(cb + cc + 0) * 64 + r] = a.x;
                Ks[(cb + cc + 1) * 64 + r] = a.y;
                Ks[(cb + cc + 2) * 64 + r] = a.z;
                Ks[(cb + cc + 3) * 64 + r] = a.w;
            }
        }
        __syncthreads();

        float acc[8][4] = {};
        #pragma unroll 2
        for (int d = 0; d < 64; d++) {
            float4 b4 = *(const float4*)&Ks[d * 64 + tx * 4];
            float4 a0 = *(const float4*)&Qs[d * 128 + ty * 8];
            float4 a1 = *(const float4*)&Qs[d * 128 + ty * 8 + 4];
            float av[8] = {a0.x, a0.y, a0.z, a0.w, a1.x, a1.y, a1.z, a1.w};
            float bv[4] = {b4.x, b4.y, b4.z, b4.w};
            #pragma unroll
            for (int i = 0; i < 8; i++)
                #pragma unroll
                for (int j = 0; j < 4; j++)
                    acc[i][j] = fmaf(av[i], bv[j], acc[i][j]);
        }

        #pragma unroll
        for (int i = 0; i < 8; i++) {
            int qi = ty * 8 + i;
            uchar4 m4 = *(const uchar4*)(mrow + (size_t)qi * NS + kt + tx * 4);
            float4 ev;
            ev.x = m4.x ? 0.0f : fexp(acc[i][0]);
            ev.y = m4.y ? 0.0f : fexp(acc[i][1]);
            ev.z = m4.z ? 0.0f : fexp(acc[i][2]);
            ev.w = m4.w ? 0.0f : fexp(acc[i][3]);
            rsum[i] += (ev.x + ev.y) + (ev.z + ev.w);
        }
    }

    // reduce across the 16 tx lanes sharing each row; write 1/sum
    #pragma unroll
    for (int i = 0; i < 8; i++) {
        float v = rsum[i];
        v += __shfl_xor_sync(0xffffffffu, v, 1);
        v += __shfl_xor_sync(0xffffffffu, v, 2);
        v += __shfl_xor_sync(0xffffffffu, v, 4);
        v += __shfl_xor_sync(0xffffffffu, v, 8);
        if (tx == 0) ls[ty * 8 + i] = v;
    }
    __syncthreads();
    if (tid < 128)
        g_rl[((size_t)(b * NH + h) * NS) + qt * 128 + tid] = 1.0f / ls[tid];
}

// ---------------- kernel 2b: attention, single normalized weight write ------
// grid (NS/128, NH, NB), 256 threads. Recomputes QK, scales exp by the
// precomputed 1/rowsum BEFORE storing: d_out weight region written ONCE.
// PV uses normalized weights -> ctx needs no post-scale.
__global__ __launch_bounds__(256, 2) void k_attn(
    const unsigned char* __restrict__ mask, float* __restrict__ wgt)
{
    extern __shared__ float sm[];
    float* Qs  = sm;            // [64][128]  (d-major, transposed)
    float* Ks  = sm + 8192;     // [64][64]   (d-major, transposed)
    float* Vs  = sm + 12288;    // [64][64]   (k-major)
    float* Ws  = sm + 16384;    // [128][64]  normalized weights tile
    float* rls = sm + 24576;    // [128]

    const int qt = blockIdx.x, h = blockIdx.y, b = blockIdx.z;
    const float* qsp = g_qs + (((size_t)(b * NH + h) * NS) + qt * 128) * NDK;
    const float* ksp = g_ks + ((size_t)(b * NH + h) * NS) * NDK;
    const float* vsp = g_vs + ((size_t)(b * NH + h) * NS) * NDK;
    float* wrow = wgt + (((size_t)(b * NH + h) * NS) + qt * 128) * NS;
    const unsigned char* mrow = mask + ((size_t)b * NS + qt * 128) * NS;

    const int tid = threadIdx.x;
    const int tx = tid & 15;        // k-col group (4 cols)
    const int ty = tid >> 4;        // q-row group (8 rows)

    // ---- load Q tile transposed -> Qs[d][qi]; fetch 1/rowsum per row
    {
        int r = tid >> 1;
        int cb = (tid & 1) * 32;
        #pragma unroll
        for (int cc = 0; cc < 32; cc += 4) {
            float4 a = *(const float4*)(qsp + (size_t)r * NDK + cb + cc);
            Qs[(cb + cc + 0) * 128 + r] = a.x;
            Qs[(cb + cc + 1) * 128 + r] = a.y;
            Qs[(cb + cc + 2) * 128 + r] = a.z;
            Qs[(cb + cc + 3) * 128 + r] = a.w;
        }
    }
    if (tid < 128)
        rls[tid] = g_rl[((size_t)(b * NH + h) * NS) + qt * 128 + tid];
    __syncthreads();

    float myrl[8];
    #pragma unroll
    for (int i = 0; i < 8; i++) myrl[i] = rls[ty * 8 + i];

    float ctx[8][4];
    #pragma unroll
    for (int i = 0; i < 8; i++)
        #pragma unroll
        for (int j = 0; j < 4; j++) ctx[i][j] = 0.0f;

    for (int kt = 0; kt < NS; kt += 64) {
        __syncthreads();   // prev PV done with Vs/Ws

        // load K tile transposed -> Ks[d][kj]
        {
            int r = tid & 63;
            int cb = (tid >> 6) * 16;
            #pragma unroll
            for (int cc = 0; cc < 16; cc += 4) {
                float4 a = *(const float4*)(ksp + (size_t)(kt + r) * NDK + cb + cc);
                Ks[(cb + cc + 0) * 64 + r] = a.x;
                Ks[(cb + cc + 1) * 64 + r] = a.y;
                Ks[(cb + cc + 2) * 64 + r] = a.z;
                Ks[(cb + cc + 3) * 64 + r] = a.w;
            }
        }
        // load V tile straight -> Vs[kj][v]
        {
            int r = tid >> 2;
            int c = (tid & 3) * 16;
            #pragma unroll
            for (int cc = 0; cc < 16; cc += 4)
                *(float4*)&Vs[r * 64 + c + cc] =
                    *(const float4*)(vsp + (size_t)(kt + r) * NDK + c + cc);
        }
        __syncthreads();

        // ---- QK: acc[8][4] over 64 d
        float acc[8][4] = {};
        #pragma unroll 2
        for (int d = 0; d < 64; d++) {
            float4 b4 = *(const float4*)&Ks[d * 64 + tx * 4];
            float4 a0 = *(const float4*)&Qs[d * 128 + ty * 8];
            float4 a1 = *(const float4*)&Qs[d * 128 + ty * 8 + 4];
            float av[8] = {a0.x, a0.y, a0.z, a0.w, a1.x, a1.y, a1.z, a1.w};
            float bv[4] = {b4.x, b4.y, b4.z, b4.w};
            #pragma unroll
            for (int i = 0; i < 8; i++)
                #pragma unroll
                for (int j = 0; j < 4; j++)
                    acc[i][j] = fmaf(av[i], bv[j], acc[i][j]);
        }

        // ---- epilogue: mask, exp, normalize, single streaming store to d_out
        #pragma unroll
        for (int i = 0; i < 8; i++) {
            int qi = ty * 8 + i;
            uchar4 m4 = *(const uchar4*)(mrow + (size_t)qi * NS + kt + tx * 4);
            float rl = myrl[i];
            float4 ev;
            ev.x = m4.x ? 0.0f : fexp(acc[i][0]) * rl;
            ev.y = m4.y ? 0.0f : fexp(acc[i][1]) * rl;
            ev.z = m4.z ? 0.0f : fexp(acc[i][2]) * rl;
            ev.w = m4.w ? 0.0f : fexp(acc[i][3]) * rl;
            __stcs((float4*)(wrow + (size_t)qi * NS + kt + tx * 4), ev);
            *(float4*)&Ws[qi * 64 + tx * 4] = ev;
        }
        __syncthreads();   // Ws visible to all

        // ---- PV: ctx += Ws[qi][k] * Vs[k][v], two k per step (normalized)
        #pragma unroll 2
        for (int k = 0; k < 64; k += 2) {
            float4 v0 = *(const float4*)&Vs[k * 64 + tx * 4];
            float4 v1 = *(const float4*)&Vs[(k + 1) * 64 + tx * 4];
            float vv0[4] = {v0.x, v0.y, v0.z, v0.w};
            float vv1[4] = {v1.x, v1.y, v1.z, v1.w};
            #pragma unroll
            for (int i = 0; i < 8; i++) {
                float2 w2 = *(const float2*)&Ws[(ty * 8 + i) * 64 + k];
                #pragma unroll
                for (int j = 0; j < 4; j++) {
                    ctx[i][j] = fmaf(w2.x, vv0[j], ctx[i][j]);
                    ctx[i][j] = fmaf(w2.y, vv1[j], ctx[i][j]);
                }
            }
        }
    }

    // ---- write ctx (already normalized) to g_ctx[b][s][h*64+v]
    #pragma unroll
    for (int i = 0; i < 8; i++) {
        int qi = ty * 8 + i;
        int s = qt * 128 + qi;
        float4 o = make_float4(ctx[i][0], ctx[i][1], ctx[i][2], ctx[i][3]);
        *(float4*)&g_ctx[((size_t)b * NS + s) * NDE + h * 64 + tx * 4] = o;
    }
}

// ---------------- kernel 3: out = LN(Q + ctx @ Wo + bo) ---------------------
__global__ __launch_bounds__(256) void k_outln(
    const float* __restrict__ Q, const float* __restrict__ Wo,
    const float* __restrict__ bo, const float* __restrict__ gamma,
    const float* __restrict__ beta, float* __restrict__ out)
{
    const int r0 = blockIdx.x * 16;
    __shared__ float Xs[16][16];
    __shared__ float Wsm[16][512];

    const int tid = threadIdx.x;
    const int row = tid >> 4;           // 0..15
    const int cb = (tid & 15) * 32;     // 32 cols per thread
    const int swz = tid & 7;

    float acc[32];
    #pragma unroll
    for (int j = 0; j < 32; j++) acc[j] = 0.0f;

    for (int k0 = 0; k0 < NDE; k0 += 16) {
        Xs[tid >> 4][tid & 15] = g_ctx[(size_t)(r0 + (tid >> 4)) * NDE + k0 + (tid & 15)];
        {
            int r = tid >> 4;
            int c0 = (tid & 15) * 32;
            #pragma unroll
            for (int cc = 0; cc < 32; cc += 4)
                *(float4*)&Wsm[r][c0 + cc] =
                    *(const float4*)(Wo + (size_t)(k0 + r) * NDE + c0 + cc);
        }
        __syncthreads();
        #pragma unroll 4
        for (int kk = 0; kk < 16; kk++) {
            float x = Xs[row][kk];
            #pragma unroll
            for (int jj = 0; jj < 8; jj++) {
                int j = (jj + swz) & 7;           // bank-swizzled access
                float4 w = *(const float4*)&Wsm[kk][cb + j * 4];
                acc[j * 4 + 0] = fmaf(x, w.x, acc[j * 4 + 0]);
                acc[j * 4 + 1] = fmaf(x, w.y, acc[j * 4 + 1]);
                acc[j * 4 + 2] = fmaf(x, w.z, acc[j * 4 + 2]);
                acc[j * 4 + 3] = fmaf(x, w.w, acc[j * 4 + 3]);
            }
        }
        __syncthreads();
    }

    // add bias + residual, compute LN statistics
    const int gr = r0 + row;
    float s1 = 0.0f, s2 = 0.0f;
    #pragma unroll
    for (int j4 = 0; j4 < 8; j4++) {
        float4 bb = *(const float4*)(bo + cb + j4 * 4);
        float4 rr = *(const float4*)(Q + (size_t)gr * NDE + cb + j4 * 4);
        float* a = &acc[j4 * 4];
        a[0] += bb.x + rr.x; a[1] += bb.y + rr.y;
        a[2] += bb.z + rr.z; a[3] += bb.w + rr.w;
        #pragma unroll
        for (int t = 0; t < 4; t++) { s1 += a[t]; s2 = fmaf(a[t], a[t], s2); }
    }
    // reduce across the 16 threads of this row (contiguous half-warp)
    #pragma unroll
    for (int d = 1; d < 16; d <<= 1) {
        s1 += __shfl_xor_sync(0xffffffffu, s1, d);
        s2 += __shfl_xor_sync(0xffffffffu, s2, d);
    }
    const float mu = s1 * (1.0f / 512.0f);
    const float var = s2 * (1.0f / 512.0f) - mu * mu;
    const float rstd = rsqrtf(var + 1e-5f);

    #pragma unroll
    for (int j4 = 0; j4 < 8; j4++) {
        float4 g = *(const float4*)(gamma + cb + j4 * 4);
        float4 be = *(const float4*)(beta + cb + j4 * 4);
        float4 o;
        o.x = (acc[j4 * 4 + 0] - mu) * rstd * g.x + be.x;
        o.y = (acc[j4 * 4 + 1] - mu) * rstd * g.y + be.y;
        o.z = (acc[j4 * 4 + 2] - mu) * rstd * g.z + be.z;
        o.w = (acc[j4 * 4 + 3] - mu) * rstd * g.w + be.w;
        *(float4*)(out + (size_t)gr * NDE + cb + j4 * 4) = o;
    }
}

// ---------------- launch ----------------------------------------------------
extern "C" void kernel_launch(void* const* d_in, const int* in_sizes, int n_in,
                              void* d_out, int out_size)
{
    const float* Q     = (const float*)d_in[0];
    const float* K     = (const float*)d_in[1];
    const float* V     = (const float*)d_in[2];
    const unsigned char* mask = (const unsigned char*)d_in[3];
    const float* Wq    = (const float*)d_in[4];
    const float* bq    = (const float*)d_in[5];
    const float* Wo    = (const float*)d_in[6];
    const float* bo    = (const float*)d_in[7];
    const float* gamma = (const float*)d_in[8];
    const float* beta  = (const float*)d_in[9];

    float* out = (float*)d_out;                      // [B,S,512] output
    float* wgt = out + (size_t)NB * NS * NDE;        // [B,H,S,S] weights

    static const int RSUM_SMEM = 12416 * 4;          // 49664 bytes
    static const int ATTN_SMEM = 24704 * 4;          // 98816 bytes
    cudaFuncSetAttribute(k_rsum, cudaFuncAttributeMaxDynamicSharedMemorySize,
                         RSUM_SMEM);
    cudaFuncSetAttribute(k_attn, cudaFuncAttributeMaxDynamicSharedMemorySize,
                         ATTN_SMEM);

    dim3 gp(NDE / 64, (NB * NS) / 64, 3);
    k_proj<<<gp, 256>>>(Q, K, V, Wq, bq);

    dim3 ga(NS / 128, NH, NB);
    k_rsum<<<ga, 256, RSUM_SMEM>>>(mask);
    k_attn<<<ga, 256, ATTN_SMEM>>>(mask, wgt);

    k_outln<<<(NB * NS) / 16, 256>>>(Q, Wo, bo, gamma, beta, out);
}

// round 11
// speedup vs baseline: 1.1089x; 1.1089x over previous
#include <cuda_runtime.h>
#include <cstdint>

#define NB 8
#define NS 2048
#define NH 8
#define NDK 64
#define NDE 512

// ---------------- scratch (device globals; no allocations allowed) ----------
__device__ float g_qs[NB * NH * NS * NDK];   // 32 MB, pre-scaled by 1/8
__device__ float g_ks[NB * NH * NS * NDK];   // 32 MB
__device__ float g_vs[NB * NH * NS * NDK];   // 32 MB
__device__ float g_ctx[NB * NS * NDE];       // 32 MB
__device__ float g_rl[NB * NH * NS];         // 512 KB: 1/rowsum per (b,h,s)

// ---------------- fast exp: FFMA-pipe polynomial (MUFU is slow on sm_103a) --
__device__ __forceinline__ float fexp(float x) {
    float y = x * 1.4426950408889634f;          // log2(e)
    y = fminf(fmaxf(y, -120.0f), 120.0f);
    float t = y + 12582912.0f;                  // round-to-nearest-int trick
    float r = t - 12582912.0f;
    float f = y - r;                            // f in [-0.5, 0.5]
    int   ei = __float_as_int(t) - 0x4B400000;  // integer value of r
    float p = 1.3333558146e-3f;
    p = fmaf(p, f, 9.6181291076e-3f);
    p = fmaf(p, f, 5.5504108665e-2f);
    p = fmaf(p, f, 2.4022650696e-1f);
    p = fmaf(p, f, 6.9314718056e-1f);
    p = fmaf(p, f, 1.0f);
    return p * __int_as_float((ei + 127) << 23);
}

// ---------------- kernel 1: projections q_s/k_s/v_s = X @ Wq + bq -----------
__global__ __launch_bounds__(256) void k_proj(
    const float* __restrict__ Q, const float* __restrict__ K,
    const float* __restrict__ V, const float* __restrict__ W,
    const float* __restrict__ bias)
{
    const int which = blockIdx.z;
    const float* X = (which == 0) ? Q : (which == 1) ? K : V;
    float* O = (which == 0) ? g_qs : (which == 1) ? g_ks : g_vs;
    const float scl = (which == 0) ? 0.125f : 1.0f;

    __shared__ float As[16][64];   // [k][m] (transposed)
    __shared__ float Bs[16][64];   // [k][n]

    const int tid = threadIdx.x;
    const int tx = tid & 15, ty = tid >> 4;
    const int m0 = blockIdx.y * 64, n0 = blockIdx.x * 64;

    float acc[4][4] = {};

    for (int k0 = 0; k0 < NDE; k0 += 16) {
        {
            int r = tid >> 2;
            int c = (tid & 3) * 4;
            float4 a = *(const float4*)(X + (size_t)(m0 + r) * NDE + k0 + c);
            As[c + 0][r] = a.x; As[c + 1][r] = a.y;
            As[c + 2][r] = a.z; As[c + 3][r] = a.w;
        }
        {
            int r = tid >> 4;
            int c = (tid & 15) * 4;
            *(float4*)&Bs[r][c] = *(const float4*)(W + (size_t)(k0 + r) * NDE + n0 + c);
        }
        __syncthreads();
        #pragma unroll
        for (int kk = 0; kk < 16; kk++) {
            float4 a = *(const float4*)&As[kk][ty * 4];
            float4 b = *(const float4*)&Bs[kk][tx * 4];
            float av[4] = {a.x, a.y, a.z, a.w};
            float bv[4] = {b.x, b.y, b.z, b.w};
            #pragma unroll
            for (int i = 0; i < 4; i++)
                #pragma unroll
                for (int j = 0; j < 4; j++)
                    acc[i][j] = fmaf(av[i], bv[j], acc[i][j]);
        }
        __syncthreads();
    }

    const int hh = n0 >> 6;                  // whole tile is one head
    float4 bi = *(const float4*)(bias + n0 + tx * 4);
    #pragma unroll
    for (int i = 0; i < 4; i++) {
        int m = m0 + ty * 4 + i;
        int bb = m >> 11;
        int ss = m & 2047;
        float4 o;
        o.x = (acc[i][0] + bi.x) * scl;
        o.y = (acc[i][1] + bi.y) * scl;
        o.z = (acc[i][2] + bi.z) * scl;
        o.w = (acc[i][3] + bi.w) * scl;
        *(float4*)(O + ((size_t)(bb * NH + hh) * NS + ss) * NDK + tx * 4) = o;
    }
}

// ---------------- kernel 2a: QK + exp + unnormalized weight store + rowsums -
// grid (NS/128, NH, NB), 256 threads. NO PV state: light registers (~60),
// proven-fast shape (R10's k_rsum + streaming stores).
__global__ __launch_bounds__(256) void k_qke(
    const unsigned char* __restrict__ mask, float* __restrict__ wgt)
{
    extern __shared__ float sm[];
    float* Qs = sm;            // [64][128]  (d-major, transposed)
    float* Ks = sm + 8192;     // [64][64]   (d-major, transposed)
    float* ls = sm + 12288;    // [128]

    const int qt = blockIdx.x, h = blockIdx.y, b = blockIdx.z;
    const float* qsp = g_qs + (((size_t)(b * NH + h) * NS) + qt * 128) * NDK;
    const float* ksp = g_ks + ((size_t)(b * NH + h) * NS) * NDK;
    float* wrow = wgt + (((size_t)(b * NH + h) * NS) + qt * 128) * NS;
    const unsigned char* mrow = mask + ((size_t)b * NS + qt * 128) * NS;

    const int tid = threadIdx.x;
    const int tx = tid & 15;        // k-col group (4 cols)
    const int ty = tid >> 4;        // q-row group (8 rows)

    // ---- load Q tile transposed -> Qs[d][qi]
    {
        int r = tid >> 1;
        int cb = (tid & 1) * 32;
        #pragma unroll
        for (int cc = 0; cc < 32; cc += 4) {
            float4 a = *(const float4*)(qsp + (size_t)r * NDK + cb + cc);
            Qs[(cb + cc + 0) * 128 + r] = a.x;
            Qs[(cb + cc + 1) * 128 + r] = a.y;
            Qs[(cb + cc + 2) * 128 + r] = a.z;
            Qs[(cb + cc + 3) * 128 + r] = a.w;
        }
    }

    float rsum[8];
    #pragma unroll
    for (int i = 0; i < 8; i++) rsum[i] = 0.0f;

    for (int kt = 0; kt < NS; kt += 64) {
        __syncthreads();
        {
            int r = tid & 63;
            int cb = (tid >> 6) * 16;
            #pragma unroll
            for (int cc = 0; cc < 16; cc += 4) {
                float4 a = *(const float4*)(ksp + (size_t)(kt + r) * NDK + cb + cc);
                Ks[(cb + cc + 0) * 64 + r] = a.x;
                Ks[(cb + cc + 1) * 64 + r] = a.y;
                Ks[(cb + cc + 2) * 64 + r] = a.z;
                Ks[(cb + cc + 3) * 64 + r] = a.w;
            }
        }
        __syncthreads();

        float acc[8][4] = {};
        #pragma unroll 2
        for (int d = 0; d < 64; d++) {
            float4 b4 = *(const float4*)&Ks[d * 64 + tx * 4];
            float4 a0 = *(const float4*)&Qs[d * 128 + ty * 8];
            float4 a1 = *(const float4*)&Qs[d * 128 + ty * 8 + 4];
            float av[8] = {a0.x, a0.y, a0.z, a0.w, a1.x, a1.y, a1.z, a1.w};
            float bv[4] = {b4.x, b4.y, b4.z, b4.w};
            #pragma unroll
            for (int i = 0; i < 8; i++)
                #pragma unroll
                for (int j = 0; j < 4; j++)
                    acc[i][j] = fmaf(av[i], bv[j], acc[i][j]);
        }

        #pragma unroll
        for (int i = 0; i < 8; i++) {
            int qi = ty * 8 + i;
            uchar4 m4 = *(const uchar4*)(mrow + (size_t)qi * NS + kt + tx * 4);
            float4 ev;
            ev.x = m4.x ? 0.0f : fexp(acc[i][0]);
            ev.y = m4.y ? 0.0f : fexp(acc[i][1]);
            ev.z = m4.z ? 0.0f : fexp(acc[i][2]);
            ev.w = m4.w ? 0.0f : fexp(acc[i][3]);
            __stcs((float4*)(wrow + (size_t)qi * NS + kt + tx * 4), ev);
            rsum[i] += (ev.x + ev.y) + (ev.z + ev.w);
        }
    }

    // reduce across the 16 tx lanes sharing each row; write 1/sum
    #pragma unroll
    for (int i = 0; i < 8; i++) {
        float v = rsum[i];
        v += __shfl_xor_sync(0xffffffffu, v, 1);
        v += __shfl_xor_sync(0xffffffffu, v, 2);
        v += __shfl_xor_sync(0xffffffffu, v, 4);
        v += __shfl_xor_sync(0xffffffffu, v, 8);
        if (tx == 0) ls[ty * 8 + i] = v;
    }
    __syncthreads();
    if (tid < 128)
        g_rl[((size_t)(b * NH + h) * NS) + qt * 128 + tid] = 1.0f / ls[tid];
}

// ---------------- kernel 2b: PV as a clean k_proj-style GEMM ----------------
// grid (NS/64, NH, NB), 256 threads, 64x64 tiles, 4x4 micro, ~50 regs.
// ctx[64 rows x 64 v] = (W * rl) @ V over K=2048. Fuses normalization:
// each weight element is loaded once, scaled by rl, written back normalized
// to d_out (single final write), and used for the GEMM.
#define WPAD 68   // 272B rows: 16B-aligned, kills the 4-way STS bank conflict
__global__ __launch_bounds__(256) void k_pv(float* __restrict__ wgt)
{
    __shared__ float WsT[16][WPAD];   // [k][q-row] transposed weight chunk
    __shared__ float Vs[16][64];      // [k][v]
    __shared__ float rls[64];

    const int qt = blockIdx.x, h = blockIdx.y, b = blockIdx.z;
    const size_t bh = (size_t)(b * NH + h);
    const int m0 = qt * 64;
    float* wrow = wgt + (bh * NS + m0) * NS;
    const float* vsp = g_vs + bh * NS * NDK;

    const int tid = threadIdx.x;
    const int tx = tid & 15, ty = tid >> 4;

    if (tid < 64) rls[tid] = g_rl[bh * NS + m0 + tid];

    // load geometry
    const int wr = tid >> 2;             // weight row 0..63
    const int wc = (tid & 3) * 4;        // weight col block (4 of 16)
    const int vr = tid >> 4;             // v row 0..15
    const int vc = (tid & 15) * 4;       // v col block
    __syncthreads();
    const float myrl = rls[wr];

    float acc[4][4] = {};

    for (int kt = 0; kt < NS; kt += 16) {
        {   // W chunk: load, normalize, write back (final), stash transposed
            float4 w4 = __ldcs((const float4*)(wrow + (size_t)wr * NS + kt + wc));
            w4.x *= myrl; w4.y *= myrl; w4.z *= myrl; w4.w *= myrl;
            __stcs((float4*)(wrow + (size_t)wr * NS + kt + wc), w4);
            WsT[wc + 0][wr] = w4.x; WsT[wc + 1][wr] = w4.y;
            WsT[wc + 2][wr] = w4.z; WsT[wc + 3][wr] = w4.w;
        }
        {   // V chunk [16][64]
            *(float4*)&Vs[vr][vc] =
                *(const float4*)(vsp + (size_t)(kt + vr) * NDK + vc);
        }
        __syncthreads();

        #pragma unroll
        for (int kk = 0; kk < 16; kk++) {
            float4 a = *(const float4*)&WsT[kk][ty * 4];
            float4 v = *(const float4*)&Vs[kk][tx * 4];
            float av[4] = {a.x, a.y, a.z, a.w};
            float bv[4] = {v.x, v.y, v.z, v.w};
            #pragma unroll
            for (int i = 0; i < 4; i++)
                #pragma unroll
                for (int j = 0; j < 4; j++)
                    acc[i][j] = fmaf(av[i], bv[j], acc[i][j]);
        }
        __syncthreads();
    }

    // write ctx (already normalized) to g_ctx[b][s][h*64+v]
    #pragma unroll
    for (int i = 0; i < 4; i++) {
        int s = m0 + ty * 4 + i;
        float4 o = make_float4(acc[i][0], acc[i][1], acc[i][2], acc[i][3]);
        *(float4*)&g_ctx[((size_t)b * NS + s) * NDE + h * 64 + tx * 4] = o;
    }
}

// ---------------- kernel 3: out = LN(Q + ctx @ Wo + bo) ---------------------
__global__ __launch_bounds__(256) void k_outln(
    const float* __restrict__ Q, const float* __restrict__ Wo,
    const float* __restrict__ bo, const float* __restrict__ gamma,
    const float* __restrict__ beta, float* __restrict__ out)
{
    const int r0 = blockIdx.x * 16;
    __shared__ float Xs[16][16];
    __shared__ float Wsm[16][512];

    const int tid = threadIdx.x;
    const int row = tid >> 4;           // 0..15
    const int cb = (tid & 15) * 32;     // 32 cols per thread
    const int swz = tid & 7;

    float acc[32];
    #pragma unroll
    for (int j = 0; j < 32; j++) acc[j] = 0.0f;

    for (int k0 = 0; k0 < NDE; k0 += 16) {
        Xs[tid >> 4][tid & 15] = g_ctx[(size_t)(r0 + (tid >> 4)) * NDE + k0 + (tid & 15)];
        {
            int r = tid >> 4;
            int c0 = (tid & 15) * 32;
            #pragma unroll
            for (int cc = 0; cc < 32; cc += 4)
                *(float4*)&Wsm[r][c0 + cc] =
                    *(const float4*)(Wo + (size_t)(k0 + r) * NDE + c0 + cc);
        }
        __syncthreads();
        #pragma unroll 4
        for (int kk = 0; kk < 16; kk++) {
            float x = Xs[row][kk];
            #pragma unroll
            for (int jj = 0; jj < 8; jj++) {
                int j = (jj + swz) & 7;           // bank-swizzled access
                float4 w = *(const float4*)&Wsm[kk][cb + j * 4];
                acc[j * 4 + 0] = fmaf(x, w.x, acc[j * 4 + 0]);
                acc[j * 4 + 1] = fmaf(x, w.y, acc[j * 4 + 1]);
                acc[j * 4 + 2] = fmaf(x, w.z, acc[j * 4 + 2]);
                acc[j * 4 + 3] = fmaf(x, w.w, acc[j * 4 + 3]);
            }
        }
        __syncthreads();
    }

    // add bias + residual, compute LN statistics
    const int gr = r0 + row;
    float s1 = 0.0f, s2 = 0.0f;
    #pragma unroll
    for (int j4 = 0; j4 < 8; j4++) {
        float4 bb = *(const float4*)(bo + cb + j4 * 4);
        float4 rr = *(const float4*)(Q + (size_t)gr * NDE + cb + j4 * 4);
        float* a = &acc[j4 * 4];
        a[0] += bb.x + rr.x; a[1] += bb.y + rr.y;
        a[2] += bb.z + rr.z; a[3] += bb.w + rr.w;
        #pragma unroll
        for (int t = 0; t < 4; t++) { s1 += a[t]; s2 = fmaf(a[t], a[t], s2); }
    }
    // reduce across the 16 threads of this row (contiguous half-warp)
    #pragma unroll
    for (int d = 1; d < 16; d <<= 1) {
        s1 += __shfl_xor_sync(0xffffffffu, s1, d);
        s2 += __shfl_xor_sync(0xffffffffu, s2, d);
    }
    const float mu = s1 * (1.0f / 512.0f);
    const float var = s2 * (1.0f / 512.0f) - mu * mu;
    const float rstd = rsqrtf(var + 1e-5f);

    #pragma unroll
    for (int j4 = 0; j4 < 8; j4++) {
        float4 g = *(const float4*)(gamma + cb + j4 * 4);
        float4 be = *(const float4*)(beta + cb + j4 * 4);
        float4 o;
        o.x = (acc[j4 * 4 + 0] - mu) * rstd * g.x + be.x;
        o.y = (acc[j4 * 4 + 1] - mu) * rstd * g.y + be.y;
        o.z = (acc[j4 * 4 + 2] - mu) * rstd * g.z + be.z;
        o.w = (acc[j4 * 4 + 3] - mu) * rstd * g.w + be.w;
        *(float4*)(out + (size_t)gr * NDE + cb + j4 * 4) = o;
    }
}

// ---------------- launch ----------------------------------------------------
extern "C" void kernel_launch(void* const* d_in, const int* in_sizes, int n_in,
                              void* d_out, int out_size)
{
    const float* Q     = (const float*)d_in[0];
    const float* K     = (const float*)d_in[1];
    const float* V     = (const float*)d_in[2];
    const unsigned char* mask = (const unsigned char*)d_in[3];
    const float* Wq    = (const float*)d_in[4];
    const float* bq    = (const float*)d_in[5];
    const float* Wo    = (const float*)d_in[6];
    const float* bo    = (const float*)d_in[7];
    const float* gamma = (const float*)d_in[8];
    const float* beta  = (const float*)d_in[9];

    float* out = (float*)d_out;                      // [B,S,512] output
    float* wgt = out + (size_t)NB * NS * NDE;        // [B,H,S,S] weights

    static const int QKE_SMEM = 12416 * 4;           // 49664 bytes
    cudaFuncSetAttribute(k_qke, cudaFuncAttributeMaxDynamicSharedMemorySize,
                         QKE_SMEM);

    dim3 gp(NDE / 64, (NB * NS) / 64, 3);
    k_proj<<<gp, 256>>>(Q, K, V, Wq, bq);

    dim3 gq(NS / 128, NH, NB);
    k_qke<<<gq, 256, QKE_SMEM>>>(mask, wgt);

    dim3 gv(NS / 64, NH, NB);
    k_pv<<<gv, 256>>>(wgt);

    k_outln<<<(NB * NS) / 16, 256>>>(Q, Wo, bo, gamma, beta, out);
}